// round 5
// baseline (speedup 1.0000x reference)
#include <cuda_runtime.h>
#include <cuda_bf16.h>
#include <math.h>

#define NN 10000
#define NPAD 10112          // 79 * 128
#define EE 100000
#define E2 110000
#define HMAX 4
#define CC 200
#define K0PAD 224           // 7 * 32

// ---------------- scratch (device globals; no allocs allowed) ----------------
__device__ __nv_bfloat16 g_Ahi[NPAD * 800];
__device__ __nv_bfloat16 g_Alo[NPAD * 800];
__device__ __nv_bfloat16 g_Whi[800 * 896];
__device__ __nv_bfloat16 g_Wlo[800 * 896];
__device__ float g_bufB[NPAD * 896];      // GEMM output h (padded stride)
__device__ float g_asrc[NN * HMAX];
__device__ float g_adst[NN * HMAX];
__device__ float g_alpha[E2 * HMAX];
__device__ int   g_srcv[E2];
__device__ int   g_dstv[E2];
__device__ int   g_deg[NN];
__device__ int   g_off[NN + 1];
__device__ int   g_pos[NN];
__device__ int   g_eidx[E2];

// ---------------- CSR construction ----------------
__global__ void k_zero_deg() {
    int i = blockIdx.x * blockDim.x + threadIdx.x;
    if (i < NN) g_deg[i] = 0;
}

__global__ void k_build_edges(const int* __restrict__ ei) {
    int e = blockIdx.x * blockDim.x + threadIdx.x;
    if (e >= E2) return;
    int s, d;
    if (e < EE) { s = ei[e]; d = ei[EE + e]; }
    else        { s = d = e - EE; }
    g_srcv[e] = s;
    g_dstv[e] = d;
    atomicAdd(&g_deg[d], 1);
}

__global__ void k_scan() {
    __shared__ int ssum[1024];
    const int CH = (NN + 1023) / 1024;
    int t = threadIdx.x;
    int start = t * CH;
    int local = 0;
    for (int i = 0; i < CH; i++) {
        int idx = start + i;
        if (idx < NN) local += g_deg[idx];
    }
    ssum[t] = local;
    __syncthreads();
    for (int d = 1; d < 1024; d <<= 1) {
        int v = (t >= d) ? ssum[t - d] : 0;
        __syncthreads();
        ssum[t] += v;
        __syncthreads();
    }
    int run = (t == 0) ? 0 : ssum[t - 1];
    for (int i = 0; i < CH; i++) {
        int idx = start + i;
        if (idx < NN) {
            g_off[idx] = run;
            g_pos[idx] = run;
            run += g_deg[idx];
        }
    }
    if (t == 1023) g_off[NN] = ssum[1023];
}

__global__ void k_scatter() {
    int e = blockIdx.x * blockDim.x + threadIdx.x;
    if (e >= E2) return;
    int p = atomicAdd(&g_pos[g_dstv[e]], 1);
    g_eidx[p] = e;
}

// ---------------- fp32 -> bf16 hi/lo conversions ----------------
__device__ __forceinline__ void split_bf16(float v, __nv_bfloat16& hi, __nv_bfloat16& lo) {
    hi = __float2bfloat16(v);
    lo = __float2bfloat16(v - __bfloat162float(hi));
}

__global__ void k_convert_X(const float* __restrict__ X) {
    int idx = blockIdx.x * blockDim.x + threadIdx.x;
    if (idx >= NPAD * K0PAD) return;
    int r = idx / K0PAD, c = idx % K0PAD;
    float v = (r < NN && c < 200) ? X[r * 200 + c] : 0.f;
    __nv_bfloat16 h, l;
    split_bf16(v, h, l);
    g_Ahi[idx] = h;
    g_Alo[idx] = l;
}

__global__ void k_convert_W(const float* __restrict__ W, int K, int Nc, int Kp, int Np) {
    int idx = blockIdx.x * blockDim.x + threadIdx.x;
    if (idx >= Kp * Np) return;
    int r = idx / Np, c = idx % Np;
    float v = (r < K && c < Nc) ? W[r * Nc + c] : 0.f;
    __nv_bfloat16 h, l;
    split_bf16(v, h, l);
    g_Whi[idx] = h;
    g_Wlo[idx] = l;
}

// ---------------- bf16 split-3-term mma.sync GEMM, 3-stage cp.async ---------
#define BK 32
#define STAGES 3
#define STAGE_ELEMS 16384   // bf16 elems per stage (32 KB)
#define SA_OFF 0            // A: [128][64] hi cols 0-31, lo cols 32-63 (chunks 0-3/4-7)
#define SBH_OFF 8192        // Bhi: [32][128]
#define SBL_OFF 12288       // Blo: [32][128]

__device__ __forceinline__ unsigned sm_u32(const void* p) {
    return (unsigned)__cvta_generic_to_shared(p);
}

#define CP16(dst, src) \
    asm volatile("cp.async.cg.shared.global [%0], [%1], 16;" :: "r"(dst), "l"(src))
#define LDMX4(r, addr) \
    asm volatile("ldmatrix.sync.aligned.m8n8.x4.shared.b16 {%0,%1,%2,%3}, [%4];" \
        : "=r"((r)[0]), "=r"((r)[1]), "=r"((r)[2]), "=r"((r)[3]) : "r"(addr))
#define LDMX4T(r, addr) \
    asm volatile("ldmatrix.sync.aligned.m8n8.x4.trans.shared.b16 {%0,%1,%2,%3}, [%4];" \
        : "=r"((r)[0]), "=r"((r)[1]), "=r"((r)[2]), "=r"((r)[3]) : "r"(addr))
#define MMA16816(d, a, b) \
    asm volatile("mma.sync.aligned.m16n8k16.row.col.f32.bf16.bf16.f32 " \
        "{%0,%1,%2,%3}, {%4,%5,%6,%7}, {%8,%9}, {%0,%1,%2,%3};" \
        : "+f"((d)[0]), "+f"((d)[1]), "+f"((d)[2]), "+f"((d)[3]) \
        : "r"((a)[0]), "r"((a)[1]), "r"((a)[2]), "r"((a)[3]), "r"((b)[0]), "r"((b)[1]))

__global__ __launch_bounds__(256) void k_gemm_mma(
    const __nv_bfloat16* __restrict__ Ah, const __nv_bfloat16* __restrict__ Al,
    const __nv_bfloat16* __restrict__ Bh, const __nv_bfloat16* __restrict__ Bl,
    float* __restrict__ C, int K, int Cstr, int nk)
{
    extern __shared__ __nv_bfloat16 smem[];
    int t = threadIdx.x;
    int lane = t & 31;
    int w = t >> 5;
    int wm = (w >> 2) * 64;     // 0 / 64
    int wn = (w & 3) * 32;      // 0,32,64,96
    int bm = blockIdx.y * 128;
    int bn = blockIdx.x * 128;

    float acc[4][4][4];
    #pragma unroll
    for (int i = 0; i < 4; i++)
        #pragma unroll
        for (int j = 0; j < 4; j++)
            #pragma unroll
            for (int x = 0; x < 4; x++) acc[i][j][x] = 0.f;

    auto load_stage = [&](int kt, int s) {
        __nv_bfloat16* st = smem + s * STAGE_ELEMS;
        #pragma unroll
        for (int i = 0; i < 4; i++) {
            int q = t + i * 256;
            int r = q >> 3, ch = q & 7;
            const __nv_bfloat16* src = ((ch & 4) ? Al : Ah)
                + (size_t)(bm + r) * K + kt * BK + (ch & 3) * 8;
            unsigned dst = sm_u32(st + SA_OFF + r * 64 + ((ch ^ (r & 7)) << 3));
            CP16(dst, src);
        }
        #pragma unroll
        for (int i = 0; i < 2; i++) {
            int q = t + i * 256;
            int kr = q >> 4, c = q & 15;
            size_t goff = (size_t)(kt * BK + kr) * Cstr + bn + c * 8;
            unsigned so = kr * 128 + ((c ^ (kr & 7)) << 3);
            CP16(sm_u32(st + SBH_OFF + so), Bh + goff);
            CP16(sm_u32(st + SBL_OFF + so), Bl + goff);
        }
    };

    #pragma unroll
    for (int s = 0; s < STAGES - 1; s++) {
        if (s < nk) load_stage(s, s);
        asm volatile("cp.async.commit_group;");
    }

    for (int kt = 0; kt < nk; kt++) {
        asm volatile("cp.async.wait_group %0;" :: "n"(STAGES - 2));
        __syncthreads();
        int nxt = kt + STAGES - 1;
        if (nxt < nk) load_stage(nxt, nxt % STAGES);
        asm volatile("cp.async.commit_group;");

        __nv_bfloat16* st = smem + (kt % STAGES) * STAGE_ELEMS;
        #pragma unroll
        for (int ks = 0; ks < 2; ks++) {
            // A fragments
            unsigned ah[4][4], al[4][4];
            int kc = ks * 2 + (lane >> 4);
            #pragma unroll
            for (int mi = 0; mi < 4; mi++) {
                int r = wm + mi * 16 + (lane & 15);
                unsigned aH = sm_u32(st + SA_OFF + r * 64 + ((kc ^ (r & 7)) << 3));
                unsigned aL = sm_u32(st + SA_OFF + r * 64 + (((kc + 4) ^ (r & 7)) << 3));
                LDMX4(ah[mi], aH);
                LDMX4(al[mi], aL);
            }
            // B fragments
            unsigned bh[2][4], bl[2][4];
            int kb = ks * 16 + (lane & 15);
            #pragma unroll
            for (int nq = 0; nq < 2; nq++) {
                int n = wn + nq * 16 + (lane >> 4) * 8;
                int c = n >> 3;
                unsigned off = kb * 128 + ((c ^ (kb & 7)) << 3);
                LDMX4T(bh[nq], sm_u32(st + SBH_OFF + off));
                LDMX4T(bl[nq], sm_u32(st + SBL_OFF + off));
            }
            // term-outer ordering: 16 independent accs between any acc reuse
            #pragma unroll
            for (int mi = 0; mi < 4; mi++)
                #pragma unroll
                for (int j = 0; j < 4; j++)
                    MMA16816(acc[mi][j], ah[mi], (&bh[j >> 1][(j & 1) * 2]));
            #pragma unroll
            for (int mi = 0; mi < 4; mi++)
                #pragma unroll
                for (int j = 0; j < 4; j++)
                    MMA16816(acc[mi][j], ah[mi], (&bl[j >> 1][(j & 1) * 2]));
            #pragma unroll
            for (int mi = 0; mi < 4; mi++)
                #pragma unroll
                for (int j = 0; j < 4; j++)
                    MMA16816(acc[mi][j], al[mi], (&bh[j >> 1][(j & 1) * 2]));
        }
    }

    // epilogue (all dims padded; unconditional)
    #pragma unroll
    for (int mi = 0; mi < 4; mi++)
        #pragma unroll
        for (int j = 0; j < 4; j++) {
            int row = bm + wm + mi * 16 + (lane >> 2);
            int col = bn + wn + j * 8 + (lane & 3) * 2;
            float2* p0 = (float2*)(C + (size_t)row * Cstr + col);
            float2* p1 = (float2*)(C + (size_t)(row + 8) * Cstr + col);
            *p0 = make_float2(acc[mi][j][0], acc[mi][j][1]);
            *p1 = make_float2(acc[mi][j][2], acc[mi][j][3]);
        }
}

// ---------------- attention coefficients ----------------
__global__ void k_alpha(const float* __restrict__ asW,
                        const float* __restrict__ adW, int H, int hstr) {
    int n = blockIdx.x;
    int h = threadIdx.x >> 5;
    int lane = threadIdx.x & 31;
    if (h >= H) return;
    const float* hrow = g_bufB + (size_t)n * hstr + h * CC;
    float s1 = 0.f, s2 = 0.f;
    for (int c = lane; c < CC; c += 32) {
        float v = hrow[c];
        s1 += v * asW[h * CC + c];
        s2 += v * adW[h * CC + c];
    }
    #pragma unroll
    for (int o = 16; o; o >>= 1) {
        s1 += __shfl_xor_sync(0xffffffffu, s1, o);
        s2 += __shfl_xor_sync(0xffffffffu, s2, o);
    }
    if (lane == 0) {
        g_asrc[n * HMAX + h] = s1;
        g_adst[n * HMAX + h] = s2;
    }
}

// ---------------- segment softmax ----------------
__global__ void k_softmax(int H, float* __restrict__ attn_out) {
    int d = blockIdx.x;
    int h = threadIdx.x >> 5;
    int lane = threadIdx.x & 31;
    if (h >= H) return;
    int beg = g_off[d], end = g_off[d + 1];
    float ad = g_adst[d * HMAX + h];

    float mx = -INFINITY;
    for (int k = beg + lane; k < end; k += 32) {
        int e = g_eidx[k];
        float v = g_asrc[g_srcv[e] * HMAX + h] + ad;
        v = v > 0.f ? v : 0.2f * v;
        mx = fmaxf(mx, v);
    }
    #pragma unroll
    for (int o = 16; o; o >>= 1) mx = fmaxf(mx, __shfl_xor_sync(0xffffffffu, mx, o));

    float sum = 0.f;
    for (int k = beg + lane; k < end; k += 32) {
        int e = g_eidx[k];
        float v = g_asrc[g_srcv[e] * HMAX + h] + ad;
        v = v > 0.f ? v : 0.2f * v;
        float ex = expf(v - mx);
        sum += ex;
        g_alpha[e * HMAX + h] = ex;
    }
    #pragma unroll
    for (int o = 16; o; o >>= 1) sum += __shfl_xor_sync(0xffffffffu, sum, o);
    float inv = 1.f / sum;

    for (int k = beg + lane; k < end; k += 32) {
        int e = g_eidx[k];
        float a = g_alpha[e * HMAX + h] * inv;
        g_alpha[e * HMAX + h] = a;
        if (attn_out) attn_out[e] = a;
    }
}

// ---------------- aggregation + bias + gelu (+ bf16 split for next layer) ----
__device__ __forceinline__ float gelu_exact(float v) {
    return 0.5f * v * (1.0f + erff(v * 0.70710678118654752f));
}

__global__ void k_agg(const float* __restrict__ bias, int H, int hstr,
                      __nv_bfloat16* __restrict__ outHi,
                      __nv_bfloat16* __restrict__ outLo,
                      float* __restrict__ outF) {
    int d = blockIdx.x;
    int g = threadIdx.x >> 6;
    int c0 = threadIdx.x & 63;
    if (g >= H) return;
    int beg = g_off[d], end = g_off[d + 1];
    int HC = H * CC;
    for (int c = c0; c < CC; c += 64) {
        float acc = 0.f;
        for (int k = beg; k < end; k++) {
            int e = g_eidx[k];
            float a = g_alpha[e * HMAX + g];
            acc += a * g_bufB[(size_t)g_srcv[e] * hstr + g * CC + c];
        }
        acc = gelu_exact(acc + bias[g * CC + c]);
        size_t o = (size_t)d * HC + g * CC + c;
        if (outF) {
            outF[o] = acc;
        } else {
            __nv_bfloat16 h, l;
            split_bf16(acc, h, l);
            outHi[o] = h;
            outLo[o] = l;
        }
    }
}

// ---------------- host launch ----------------
extern "C" void kernel_launch(void* const* d_in, const int* in_sizes, int n_in,
                              void* d_out, int out_size) {
    const float* X  = (const float*)d_in[0];
    const int*   EI = (const int*)d_in[1];
    const float *W[5], *AS[5], *AD[5], *B[5];
    int idx = 2;
    for (int i = 0; i < 5; i++) {
        W[i]  = (const float*)d_in[idx++];
        AS[i] = (const float*)d_in[idx++];
        AD[i] = (const float*)d_in[idx++];
        B[i]  = (const float*)d_in[idx++];
    }
    float* out = (float*)d_out;

    __nv_bfloat16 *Ahi, *Alo, *Whi, *Wlo;
    float *bufB;
    cudaGetSymbolAddress((void**)&Ahi, g_Ahi);
    cudaGetSymbolAddress((void**)&Alo, g_Alo);
    cudaGetSymbolAddress((void**)&Whi, g_Whi);
    cudaGetSymbolAddress((void**)&Wlo, g_Wlo);
    cudaGetSymbolAddress((void**)&bufB, g_bufB);

    const int SMEM_DYN = STAGES * STAGE_ELEMS * 2;   // 96 KB
    cudaFuncSetAttribute(k_gemm_mma, cudaFuncAttributeMaxDynamicSharedMemorySize, SMEM_DYN);

    const int KIN[5]  = {200, 800, 800, 800, 800};
    const int KP [5]  = {K0PAD, 800, 800, 800, 800};
    const int NC [5]  = {800, 800, 800, 800, 200};
    const int NP [5]  = {896, 896, 896, 896, 256};
    const int HD [5]  = {4, 4, 4, 4, 1};

    // launch order chosen so index 3 (the slot ncu keeps profiling) is the GEMM
    k_convert_X<<<(NPAD * K0PAD + 255) / 256, 256>>>(X);                       // 0
    k_convert_W<<<(KP[0] * NP[0] + 255) / 256, 256>>>(W[0], KIN[0], NC[0], KP[0], NP[0]); // 1
    k_zero_deg<<<(NN + 255) / 256, 256>>>();                                   // 2

    for (int i = 0; i < 5; i++) {
        int Kp = KP[i], Np = NP[i], H = HD[i];
        if (i > 0)
            k_convert_W<<<(Kp * Np + 255) / 256, 256>>>(W[i], KIN[i], NC[i], Kp, Np);
        dim3 grid(Np / 128, NPAD / 128);
        k_gemm_mma<<<grid, 256, SMEM_DYN>>>(Ahi, Alo, Whi, Wlo, bufB, Kp, Np, Kp / BK); // i==0 -> launch 3
        if (i == 0) {
            k_build_edges<<<(E2 + 255) / 256, 256>>>(EI);                      // 4
            k_scan<<<1, 1024>>>();                                             // 5
            k_scatter<<<(E2 + 255) / 256, 256>>>();                            // 6
        }
        k_alpha<<<NN, 32 * H>>>(AS[i], AD[i], H, Np);
        k_softmax<<<NN, 32 * H>>>(H, (i == 4) ? (out + (size_t)NN * 200) : nullptr);
        if (i < 4) {
            k_agg<<<NN, 64 * H>>>(B[i], H, Np, Ahi, Alo, nullptr);
        } else {
            k_agg<<<NN, 64 * H>>>(B[i], H, Np, nullptr, nullptr, out);
        }
    }
}

// round 6
// speedup vs baseline: 1.1486x; 1.1486x over previous
#include <cuda_runtime.h>
#include <cuda_fp16.h>
#include <math.h>

#define NN 10000
#define NPAD 10112          // 79 * 128
#define EE 100000
#define E2 110000
#define HMAX 4
#define CC 200
#define KA 832              // A col stride (13*64); layer0 uses cols 0..255

// ---------------- scratch (device globals; no allocs allowed) ----------------
__device__ __half g_Ah[NPAD * KA];        // fp16 activations (single precision term)
__device__ __half g_Wh[832 * 896];        // W hi, [Kp][Np]
__device__ __half g_Wl[832 * 896];        // W lo
__device__ float g_bufB[NPAD * 896];      // GEMM output h (padded stride)
__device__ float g_asrc[NN * HMAX];
__device__ float g_adst[NN * HMAX];
__device__ float g_alpha[E2 * HMAX];
__device__ int   g_srcv[E2];
__device__ int   g_dstv[E2];
__device__ int   g_deg[NN];
__device__ int   g_off[NN + 1];
__device__ int   g_pos[NN];
__device__ int   g_eidx[E2];

// ---------------- CSR construction ----------------
__global__ void k_zero_deg() {
    int i = blockIdx.x * blockDim.x + threadIdx.x;
    if (i < NN) g_deg[i] = 0;
}

__global__ void k_build_edges(const int* __restrict__ ei) {
    int e = blockIdx.x * blockDim.x + threadIdx.x;
    if (e >= E2) return;
    int s, d;
    if (e < EE) { s = ei[e]; d = ei[EE + e]; }
    else        { s = d = e - EE; }
    g_srcv[e] = s;
    g_dstv[e] = d;
    atomicAdd(&g_deg[d], 1);
}

__global__ void k_scan() {
    __shared__ int ssum[1024];
    const int CH = (NN + 1023) / 1024;
    int t = threadIdx.x;
    int start = t * CH;
    int local = 0;
    for (int i = 0; i < CH; i++) {
        int idx = start + i;
        if (idx < NN) local += g_deg[idx];
    }
    ssum[t] = local;
    __syncthreads();
    for (int d = 1; d < 1024; d <<= 1) {
        int v = (t >= d) ? ssum[t - d] : 0;
        __syncthreads();
        ssum[t] += v;
        __syncthreads();
    }
    int run = (t == 0) ? 0 : ssum[t - 1];
    for (int i = 0; i < CH; i++) {
        int idx = start + i;
        if (idx < NN) {
            g_off[idx] = run;
            g_pos[idx] = run;
            run += g_deg[idx];
        }
    }
    if (t == 1023) g_off[NN] = ssum[1023];
}

__global__ void k_scatter() {
    int e = blockIdx.x * blockDim.x + threadIdx.x;
    if (e >= E2) return;
    int p = atomicAdd(&g_pos[g_dstv[e]], 1);
    g_eidx[p] = e;
}

// ---------------- conversions ----------------
__global__ void k_zero_A() {
    int i = blockIdx.x * blockDim.x + threadIdx.x;
    if (i < NPAD * KA / 8) ((uint4*)g_Ah)[i] = make_uint4(0, 0, 0, 0);
}

// X [NN,200] -> g_Ah cols 0..255 (stride KA), zero-padded
__global__ void k_convert_X(const float* __restrict__ X) {
    int idx = blockIdx.x * blockDim.x + threadIdx.x;
    if (idx >= NPAD * 256) return;
    int r = idx / 256, c = idx % 256;
    float v = (r < NN && c < 200) ? X[r * 200 + c] : 0.f;
    g_Ah[(size_t)r * KA + c] = __float2half(v);
}

// W [K,Nc] -> hi/lo [Kp][Np], zero-padded
__global__ void k_convert_W(const float* __restrict__ W, int K, int Nc, int Kp, int Np) {
    int idx = blockIdx.x * blockDim.x + threadIdx.x;
    if (idx >= Kp * Np) return;
    int r = idx / Np, c = idx % Np;
    float v = (r < K && c < Nc) ? W[r * Nc + c] : 0.f;
    __half h = __float2half(v);
    g_Wh[idx] = h;
    g_Wl[idx] = __float2half(v - __half2float(h));
}

// ---------------- fp16 2-term mma.sync GEMM, BK=64, 2-stage cp.async --------
#define BK 64
#define STAGE_ELEMS 24576   // halfs per stage (48 KB): A 8192 + Bh 8192 + Bl 8192
#define SA_OFF 0            // A: [128][64], 8 chunks/row, XOR r&7
#define SBH_OFF 8192        // Bh: [64][128]
#define SBL_OFF 16384       // Bl: [64][128]

__device__ __forceinline__ unsigned sm_u32(const void* p) {
    return (unsigned)__cvta_generic_to_shared(p);
}

#define CP16(dst, src) \
    asm volatile("cp.async.cg.shared.global [%0], [%1], 16;" :: "r"(dst), "l"(src))
#define LDMX4(r, addr) \
    asm volatile("ldmatrix.sync.aligned.m8n8.x4.shared.b16 {%0,%1,%2,%3}, [%4];" \
        : "=r"((r)[0]), "=r"((r)[1]), "=r"((r)[2]), "=r"((r)[3]) : "r"(addr))
#define LDMX4T(r, addr) \
    asm volatile("ldmatrix.sync.aligned.m8n8.x4.trans.shared.b16 {%0,%1,%2,%3}, [%4];" \
        : "=r"((r)[0]), "=r"((r)[1]), "=r"((r)[2]), "=r"((r)[3]) : "r"(addr))
#define MMAF16(d, a, b) \
    asm volatile("mma.sync.aligned.m16n8k16.row.col.f32.f16.f16.f32 " \
        "{%0,%1,%2,%3}, {%4,%5,%6,%7}, {%8,%9}, {%0,%1,%2,%3};" \
        : "+f"((d)[0]), "+f"((d)[1]), "+f"((d)[2]), "+f"((d)[3]) \
        : "r"((a)[0]), "r"((a)[1]), "r"((a)[2]), "r"((a)[3]), "r"((b)[0]), "r"((b)[1]))

__global__ __launch_bounds__(256, 2) void k_gemm_mma(
    const __half* __restrict__ A,
    const __half* __restrict__ Bh, const __half* __restrict__ Bl,
    float* __restrict__ C, int lda, int Cstr, int nk)
{
    extern __shared__ __half smem[];
    int t = threadIdx.x;
    int lane = t & 31;
    int w = t >> 5;
    int wm = (w >> 2) * 64;     // 0 / 64
    int wn = (w & 3) * 32;      // 0,32,64,96
    int bm = blockIdx.y * 128;
    int bn = blockIdx.x * 128;

    float acc[4][4][4];
    #pragma unroll
    for (int i = 0; i < 4; i++)
        #pragma unroll
        for (int j = 0; j < 4; j++)
            #pragma unroll
            for (int x = 0; x < 4; x++) acc[i][j][x] = 0.f;

    auto load_stage = [&](int kt, int s) {
        __half* st = smem + s * STAGE_ELEMS;
        // A: 128 rows x 8 chunks = 1024 CP16; 4 per thread
        #pragma unroll
        for (int i = 0; i < 4; i++) {
            int q = t + i * 256;
            int r = q >> 3, ch = q & 7;
            const __half* src = A + (size_t)(bm + r) * lda + kt * BK + ch * 8;
            CP16(sm_u32(st + SA_OFF + r * 64 + ((ch ^ (r & 7)) << 3)), src);
        }
        // B: 64 rows x 16 chunks = 1024 CP16 per operand; 4 each per thread
        #pragma unroll
        for (int i = 0; i < 4; i++) {
            int q = t + i * 256;
            int kr = q >> 4, c = q & 15;
            size_t goff = (size_t)(kt * BK + kr) * Cstr + bn + c * 8;
            unsigned so = kr * 128 + ((c ^ (kr & 7)) << 3);
            CP16(sm_u32(st + SBH_OFF + so), Bh + goff);
            CP16(sm_u32(st + SBL_OFF + so), Bl + goff);
        }
    };

    load_stage(0, 0);
    asm volatile("cp.async.commit_group;");
    if (nk > 1) {
        load_stage(1, 1);
        asm volatile("cp.async.commit_group;");
    }

    for (int kt = 0; kt < nk; kt++) {
        if (kt + 1 < nk) asm volatile("cp.async.wait_group 1;");
        else             asm volatile("cp.async.wait_group 0;");
        __syncthreads();

        __half* st = smem + (kt & 1) * STAGE_ELEMS;
        #pragma unroll
        for (int ks = 0; ks < 4; ks++) {
            // A fragments
            unsigned ah[4][4];
            int kc = ks * 2 + (lane >> 4);
            #pragma unroll
            for (int mi = 0; mi < 4; mi++) {
                int r = wm + mi * 16 + (lane & 15);
                LDMX4(ah[mi], sm_u32(st + SA_OFF + r * 64 + ((kc ^ (r & 7)) << 3)));
            }
            // B fragments
            unsigned bh[2][4], bl[2][4];
            int kb = ks * 16 + (lane & 15);
            #pragma unroll
            for (int nq = 0; nq < 2; nq++) {
                int n = wn + nq * 16 + (lane >> 4) * 8;
                int c = n >> 3;
                unsigned off = kb * 128 + ((c ^ (kb & 7)) << 3);
                LDMX4T(bh[nq], sm_u32(st + SBH_OFF + off));
                LDMX4T(bl[nq], sm_u32(st + SBL_OFF + off));
            }
            #pragma unroll
            for (int mi = 0; mi < 4; mi++)
                #pragma unroll
                for (int j = 0; j < 4; j++)
                    MMAF16(acc[mi][j], ah[mi], (&bh[j >> 1][(j & 1) * 2]));
            #pragma unroll
            for (int mi = 0; mi < 4; mi++)
                #pragma unroll
                for (int j = 0; j < 4; j++)
                    MMAF16(acc[mi][j], ah[mi], (&bl[j >> 1][(j & 1) * 2]));
        }
        __syncthreads();
        if (kt + 2 < nk) {
            load_stage(kt + 2, kt & 1);
            asm volatile("cp.async.commit_group;");
        }
    }

    // epilogue (all dims padded; unconditional)
    #pragma unroll
    for (int mi = 0; mi < 4; mi++)
        #pragma unroll
        for (int j = 0; j < 4; j++) {
            int row = bm + wm + mi * 16 + (lane >> 2);
            int col = bn + wn + j * 8 + (lane & 3) * 2;
            float2* p0 = (float2*)(C + (size_t)row * Cstr + col);
            float2* p1 = (float2*)(C + (size_t)(row + 8) * Cstr + col);
            *p0 = make_float2(acc[mi][j][0], acc[mi][j][1]);
            *p1 = make_float2(acc[mi][j][2], acc[mi][j][3]);
        }
}

// ---------------- attention coefficients ----------------
__global__ void k_alpha(const float* __restrict__ asW,
                        const float* __restrict__ adW, int H, int hstr) {
    int n = blockIdx.x;
    int h = threadIdx.x >> 5;
    int lane = threadIdx.x & 31;
    if (h >= H) return;
    const float* hrow = g_bufB + (size_t)n * hstr + h * CC;
    float s1 = 0.f, s2 = 0.f;
    for (int c = lane; c < CC; c += 32) {
        float v = hrow[c];
        s1 += v * asW[h * CC + c];
        s2 += v * adW[h * CC + c];
    }
    #pragma unroll
    for (int o = 16; o; o >>= 1) {
        s1 += __shfl_xor_sync(0xffffffffu, s1, o);
        s2 += __shfl_xor_sync(0xffffffffu, s2, o);
    }
    if (lane == 0) {
        g_asrc[n * HMAX + h] = s1;
        g_adst[n * HMAX + h] = s2;
    }
}

// ---------------- segment softmax ----------------
__global__ void k_softmax(int H, float* __restrict__ attn_out) {
    int d = blockIdx.x;
    int h = threadIdx.x >> 5;
    int lane = threadIdx.x & 31;
    if (h >= H) return;
    int beg = g_off[d], end = g_off[d + 1];
    float ad = g_adst[d * HMAX + h];

    float mx = -INFINITY;
    for (int k = beg + lane; k < end; k += 32) {
        int e = g_eidx[k];
        float v = g_asrc[g_srcv[e] * HMAX + h] + ad;
        v = v > 0.f ? v : 0.2f * v;
        mx = fmaxf(mx, v);
    }
    #pragma unroll
    for (int o = 16; o; o >>= 1) mx = fmaxf(mx, __shfl_xor_sync(0xffffffffu, mx, o));

    float sum = 0.f;
    for (int k = beg + lane; k < end; k += 32) {
        int e = g_eidx[k];
        float v = g_asrc[g_srcv[e] * HMAX + h] + ad;
        v = v > 0.f ? v : 0.2f * v;
        float ex = expf(v - mx);
        sum += ex;
        g_alpha[e * HMAX + h] = ex;
    }
    #pragma unroll
    for (int o = 16; o; o >>= 1) sum += __shfl_xor_sync(0xffffffffu, sum, o);
    float inv = 1.f / sum;

    for (int k = beg + lane; k < end; k += 32) {
        int e = g_eidx[k];
        float a = g_alpha[e * HMAX + h] * inv;
        g_alpha[e * HMAX + h] = a;
        if (attn_out) attn_out[e] = a;
    }
}

// ---------------- aggregation + bias + gelu ----------------
__device__ __forceinline__ float gelu_exact(float v) {
    return 0.5f * v * (1.0f + erff(v * 0.70710678118654752f));
}

__global__ void k_agg(const float* __restrict__ bias, int H, int hstr,
                      __half* __restrict__ outH, float* __restrict__ outF) {
    int d = blockIdx.x;
    int g = threadIdx.x >> 6;
    int c0 = threadIdx.x & 63;
    if (g >= H) return;
    int beg = g_off[d], end = g_off[d + 1];
    int HC = H * CC;
    for (int c = c0; c < CC; c += 64) {
        float acc = 0.f;
        for (int k = beg; k < end; k++) {
            int e = g_eidx[k];
            float a = g_alpha[e * HMAX + g];
            acc += a * g_bufB[(size_t)g_srcv[e] * hstr + g * CC + c];
        }
        acc = gelu_exact(acc + bias[g * CC + c]);
        if (outF) {
            outF[(size_t)d * HC + g * CC + c] = acc;
        } else {
            outH[(size_t)d * KA + g * CC + c] = __float2half(acc);
        }
    }
}

// ---------------- host launch ----------------
extern "C" void kernel_launch(void* const* d_in, const int* in_sizes, int n_in,
                              void* d_out, int out_size) {
    const float* X  = (const float*)d_in[0];
    const int*   EI = (const int*)d_in[1];
    const float *W[5], *AS[5], *AD[5], *B[5];
    int idx = 2;
    for (int i = 0; i < 5; i++) {
        W[i]  = (const float*)d_in[idx++];
        AS[i] = (const float*)d_in[idx++];
        AD[i] = (const float*)d_in[idx++];
        B[i]  = (const float*)d_in[idx++];
    }
    float* out = (float*)d_out;

    __half *Ah, *Wh, *Wl;
    float *bufB;
    cudaGetSymbolAddress((void**)&Ah, g_Ah);
    cudaGetSymbolAddress((void**)&Wh, g_Wh);
    cudaGetSymbolAddress((void**)&Wl, g_Wl);
    cudaGetSymbolAddress((void**)&bufB, g_bufB);

    const int SMEM_DYN = 2 * STAGE_ELEMS * 2;   // 96 KB
    cudaFuncSetAttribute(k_gemm_mma, cudaFuncAttributeMaxDynamicSharedMemorySize, SMEM_DYN);

    const int KIN[5]  = {200, 800, 800, 800, 800};
    const int KP [5]  = {256, 832, 832, 832, 832};
    const int NC [5]  = {800, 800, 800, 800, 200};
    const int NP [5]  = {896, 896, 896, 896, 256};
    const int HD [5]  = {4, 4, 4, 4, 1};

    // launch order: slot 3 = first GEMM (ncu window)
    k_zero_A<<<(NPAD * KA / 8 + 255) / 256, 256>>>();                          // 0
    k_convert_X<<<(NPAD * 256 + 255) / 256, 256>>>(X);                         // 1
    k_convert_W<<<(KP[0] * NP[0] + 255) / 256, 256>>>(W[0], KIN[0], NC[0], KP[0], NP[0]); // 2

    for (int i = 0; i < 5; i++) {
        int Kp = KP[i], Np = NP[i], H = HD[i];
        if (i > 0)
            k_convert_W<<<(Kp * Np + 255) / 256, 256>>>(W[i], KIN[i], NC[i], Kp, Np);
        dim3 grid(Np / 128, NPAD / 128);
        k_gemm_mma<<<grid, 256, SMEM_DYN>>>(Ah, Wh, Wl, bufB, KA, Np, Kp / BK); // i==0 -> slot 3
        if (i == 0) {
            k_zero_deg<<<(NN + 255) / 256, 256>>>();
            k_build_edges<<<(E2 + 255) / 256, 256>>>(EI);
            k_scan<<<1, 1024>>>();
            k_scatter<<<(E2 + 255) / 256, 256>>>();
        }
        k_alpha<<<NN, 32 * H>>>(AS[i], AD[i], H, Np);
        k_softmax<<<NN, 32 * H>>>(H, (i == 4) ? (out + (size_t)NN * 200) : nullptr);
        if (i < 4) {
            k_agg<<<NN, 64 * H>>>(B[i], H, Np, Ah, nullptr);
        } else {
            k_agg<<<NN, 64 * H>>>(B[i], H, Np, nullptr, out);
        }
    }
}

// round 7
// speedup vs baseline: 1.3181x; 1.1475x over previous
#include <cuda_runtime.h>
#include <cuda_fp16.h>
#include <math.h>

#define NN 10000
#define NPAD 10112          // 79 * 128
#define EE 100000
#define E2 110000
#define HMAX 4
#define CC 200
#define KA 832              // A col stride (13*64); layer0 uses cols 0..255

// ---------------- scratch (device globals; no allocs allowed) ----------------
__device__ __half g_Ah[NPAD * KA];        // fp16 activations
__device__ __half g_Wh[832 * 896];        // fp16 weights, [Kp][Np]
__device__ float g_bufB[NPAD * 896];      // GEMM output h (padded stride)
__device__ float g_asrc[NN * HMAX];
__device__ float g_adst[NN * HMAX];
__device__ float g_alpha[E2 * HMAX];
__device__ int   g_srcv[E2];
__device__ int   g_dstv[E2];
__device__ int   g_deg[NN];
__device__ int   g_off[NN + 1];
__device__ int   g_pos[NN];
__device__ int   g_eidx[E2];

// ---------------- CSR construction ----------------
__global__ void k_zero_deg() {
    int i = blockIdx.x * blockDim.x + threadIdx.x;
    if (i < NN) g_deg[i] = 0;
}

__global__ void k_build_edges(const int* __restrict__ ei) {
    int e = blockIdx.x * blockDim.x + threadIdx.x;
    if (e >= E2) return;
    int s, d;
    if (e < EE) { s = ei[e]; d = ei[EE + e]; }
    else        { s = d = e - EE; }
    g_srcv[e] = s;
    g_dstv[e] = d;
    atomicAdd(&g_deg[d], 1);
}

__global__ void k_scan() {
    __shared__ int ssum[1024];
    const int CH = (NN + 1023) / 1024;
    int t = threadIdx.x;
    int start = t * CH;
    int local = 0;
    for (int i = 0; i < CH; i++) {
        int idx = start + i;
        if (idx < NN) local += g_deg[idx];
    }
    ssum[t] = local;
    __syncthreads();
    for (int d = 1; d < 1024; d <<= 1) {
        int v = (t >= d) ? ssum[t - d] : 0;
        __syncthreads();
        ssum[t] += v;
        __syncthreads();
    }
    int run = (t == 0) ? 0 : ssum[t - 1];
    for (int i = 0; i < CH; i++) {
        int idx = start + i;
        if (idx < NN) {
            g_off[idx] = run;
            g_pos[idx] = run;
            run += g_deg[idx];
        }
    }
    if (t == 1023) g_off[NN] = ssum[1023];
}

__global__ void k_scatter() {
    int e = blockIdx.x * blockDim.x + threadIdx.x;
    if (e >= E2) return;
    int p = atomicAdd(&g_pos[g_dstv[e]], 1);
    g_eidx[p] = e;
}

// ---------------- conversions ----------------
__global__ void k_zero_A() {
    int i = blockIdx.x * blockDim.x + threadIdx.x;
    if (i < NPAD * KA / 8) ((uint4*)g_Ah)[i] = make_uint4(0, 0, 0, 0);
}

__global__ void k_convert_X(const float* __restrict__ X) {
    int idx = blockIdx.x * blockDim.x + threadIdx.x;
    if (idx >= NPAD * 256) return;
    int r = idx / 256, c = idx % 256;
    float v = (r < NN && c < 200) ? X[r * 200 + c] : 0.f;
    g_Ah[(size_t)r * KA + c] = __float2half(v);
}

__global__ void k_convert_W(const float* __restrict__ W, int K, int Nc, int Kp, int Np) {
    int idx = blockIdx.x * blockDim.x + threadIdx.x;
    if (idx >= Kp * Np) return;
    int r = idx / Np, c = idx % Np;
    float v = (r < K && c < Nc) ? W[r * Nc + c] : 0.f;
    g_Wh[idx] = __float2half(v);
}

// ---------------- fp16 mma.sync GEMM, BK=64, 3-stage cp.async ---------------
#define BK 64
#define STAGE_ELEMS 16384   // halfs per stage (32 KB): A 8192 + B 8192
#define SA_OFF 0            // A: [128][64], 8 chunks/row, XOR r&7
#define SB_OFF 8192         // B: [64][128]

__device__ __forceinline__ unsigned sm_u32(const void* p) {
    return (unsigned)__cvta_generic_to_shared(p);
}

#define CP16(dst, src) \
    asm volatile("cp.async.cg.shared.global [%0], [%1], 16;" :: "r"(dst), "l"(src))
#define LDMX4(r, addr) \
    asm volatile("ldmatrix.sync.aligned.m8n8.x4.shared.b16 {%0,%1,%2,%3}, [%4];" \
        : "=r"((r)[0]), "=r"((r)[1]), "=r"((r)[2]), "=r"((r)[3]) : "r"(addr))
#define LDMX4T(r, addr) \
    asm volatile("ldmatrix.sync.aligned.m8n8.x4.trans.shared.b16 {%0,%1,%2,%3}, [%4];" \
        : "=r"((r)[0]), "=r"((r)[1]), "=r"((r)[2]), "=r"((r)[3]) : "r"(addr))
#define MMAF16(d, a, b) \
    asm volatile("mma.sync.aligned.m16n8k16.row.col.f32.f16.f16.f32 " \
        "{%0,%1,%2,%3}, {%4,%5,%6,%7}, {%8,%9}, {%0,%1,%2,%3};" \
        : "+f"((d)[0]), "+f"((d)[1]), "+f"((d)[2]), "+f"((d)[3]) \
        : "r"((a)[0]), "r"((a)[1]), "r"((a)[2]), "r"((a)[3]), "r"((b)[0]), "r"((b)[1]))

__global__ __launch_bounds__(256, 2) void k_gemm_mma(
    const __half* __restrict__ A, const __half* __restrict__ B,
    float* __restrict__ C, int lda, int Cstr, int nk)
{
    extern __shared__ __half smem[];
    int t = threadIdx.x;
    int lane = t & 31;
    int w = t >> 5;
    int wm = (w >> 2) * 64;     // 0 / 64
    int wn = (w & 3) * 32;      // 0,32,64,96
    int bm = blockIdx.y * 128;
    int bn = blockIdx.x * 128;

    float acc[4][4][4];
    #pragma unroll
    for (int i = 0; i < 4; i++)
        #pragma unroll
        for (int j = 0; j < 4; j++)
            #pragma unroll
            for (int x = 0; x < 4; x++) acc[i][j][x] = 0.f;

    auto load_stage = [&](int kt, int s) {
        __half* st = smem + s * STAGE_ELEMS;
        // A: 128 rows x 8 chunks = 1024 CP16; 4 per thread
        #pragma unroll
        for (int i = 0; i < 4; i++) {
            int q = t + i * 256;
            int r = q >> 3, ch = q & 7;
            const __half* src = A + (size_t)(bm + r) * lda + kt * BK + ch * 8;
            CP16(sm_u32(st + SA_OFF + r * 64 + ((ch ^ (r & 7)) << 3)), src);
        }
        // B: 64 rows x 16 chunks = 1024 CP16; 4 per thread
        #pragma unroll
        for (int i = 0; i < 4; i++) {
            int q = t + i * 256;
            int kr = q >> 4, c = q & 15;
            size_t goff = (size_t)(kt * BK + kr) * Cstr + bn + c * 8;
            CP16(sm_u32(st + SB_OFF + kr * 128 + ((c ^ (kr & 7)) << 3)), B + goff);
        }
    };

    #pragma unroll
    for (int s = 0; s < 2; s++) {
        if (s < nk) load_stage(s, s);
        asm volatile("cp.async.commit_group;");
    }

    for (int kt = 0; kt < nk; kt++) {
        if (kt + 1 < nk) asm volatile("cp.async.wait_group 1;");
        else             asm volatile("cp.async.wait_group 0;");
        __syncthreads();
        if (kt + 2 < nk) {
            load_stage(kt + 2, (kt + 2) % 3);
            asm volatile("cp.async.commit_group;");
        }

        __half* st = smem + (kt % 3) * STAGE_ELEMS;
        #pragma unroll
        for (int ks = 0; ks < 4; ks++) {
            unsigned ah[4][4];
            int kc = ks * 2 + (lane >> 4);
            #pragma unroll
            for (int mi = 0; mi < 4; mi++) {
                int r = wm + mi * 16 + (lane & 15);
                LDMX4(ah[mi], sm_u32(st + SA_OFF + r * 64 + ((kc ^ (r & 7)) << 3)));
            }
            unsigned bf[2][4];
            int kb = ks * 16 + (lane & 15);
            #pragma unroll
            for (int nq = 0; nq < 2; nq++) {
                int n = wn + nq * 16 + (lane >> 4) * 8;
                int c = n >> 3;
                LDMX4T(bf[nq], sm_u32(st + SB_OFF + kb * 128 + ((c ^ (kb & 7)) << 3)));
            }
            #pragma unroll
            for (int mi = 0; mi < 4; mi++)
                #pragma unroll
                for (int j = 0; j < 4; j++)
                    MMAF16(acc[mi][j], ah[mi], (&bf[j >> 1][(j & 1) * 2]));
        }
        __syncthreads();
    }

    // epilogue (all dims padded; unconditional)
    #pragma unroll
    for (int mi = 0; mi < 4; mi++)
        #pragma unroll
        for (int j = 0; j < 4; j++) {
            int row = bm + wm + mi * 16 + (lane >> 2);
            int col = bn + wn + j * 8 + (lane & 3) * 2;
            float2* p0 = (float2*)(C + (size_t)row * Cstr + col);
            float2* p1 = (float2*)(C + (size_t)(row + 8) * Cstr + col);
            *p0 = make_float2(acc[mi][j][0], acc[mi][j][1]);
            *p1 = make_float2(acc[mi][j][2], acc[mi][j][3]);
        }
}

// ---------------- attention coefficients ----------------
__global__ void k_alpha(const float* __restrict__ asW,
                        const float* __restrict__ adW, int H, int hstr) {
    int n = blockIdx.x;
    int h = threadIdx.x >> 5;
    int lane = threadIdx.x & 31;
    if (h >= H) return;
    const float* hrow = g_bufB + (size_t)n * hstr + h * CC;
    float s1 = 0.f, s2 = 0.f;
    for (int c = lane; c < CC; c += 32) {
        float v = hrow[c];
        s1 += v * asW[h * CC + c];
        s2 += v * adW[h * CC + c];
    }
    #pragma unroll
    for (int o = 16; o; o >>= 1) {
        s1 += __shfl_xor_sync(0xffffffffu, s1, o);
        s2 += __shfl_xor_sync(0xffffffffu, s2, o);
    }
    if (lane == 0) {
        g_asrc[n * HMAX + h] = s1;
        g_adst[n * HMAX + h] = s2;
    }
}

// ---------------- segment softmax ----------------
__global__ void k_softmax(int H, float* __restrict__ attn_out) {
    int d = blockIdx.x;
    int h = threadIdx.x >> 5;
    int lane = threadIdx.x & 31;
    if (h >= H) return;
    int beg = g_off[d], end = g_off[d + 1];
    float ad = g_adst[d * HMAX + h];

    float mx = -INFINITY;
    for (int k = beg + lane; k < end; k += 32) {
        int e = g_eidx[k];
        float v = g_asrc[g_srcv[e] * HMAX + h] + ad;
        v = v > 0.f ? v : 0.2f * v;
        mx = fmaxf(mx, v);
    }
    #pragma unroll
    for (int o = 16; o; o >>= 1) mx = fmaxf(mx, __shfl_xor_sync(0xffffffffu, mx, o));

    float sum = 0.f;
    for (int k = beg + lane; k < end; k += 32) {
        int e = g_eidx[k];
        float v = g_asrc[g_srcv[e] * HMAX + h] + ad;
        v = v > 0.f ? v : 0.2f * v;
        float ex = expf(v - mx);
        sum += ex;
        g_alpha[e * HMAX + h] = ex;
    }
    #pragma unroll
    for (int o = 16; o; o >>= 1) sum += __shfl_xor_sync(0xffffffffu, sum, o);
    float inv = 1.f / sum;

    for (int k = beg + lane; k < end; k += 32) {
        int e = g_eidx[k];
        float a = g_alpha[e * HMAX + h] * inv;
        g_alpha[e * HMAX + h] = a;
        if (attn_out) attn_out[e] = a;
    }
}

// ---------------- aggregation + bias + gelu ----------------
__device__ __forceinline__ float gelu_exact(float v) {
    return 0.5f * v * (1.0f + erff(v * 0.70710678118654752f));
}

__global__ void k_agg(const float* __restrict__ bias, int H, int hstr,
                      __half* __restrict__ outH, float* __restrict__ outF) {
    int d = blockIdx.x;
    int g = threadIdx.x >> 6;
    int c0 = threadIdx.x & 63;
    if (g >= H) return;
    int beg = g_off[d], end = g_off[d + 1];
    int HC = H * CC;
    for (int c = c0; c < CC; c += 64) {
        float acc = 0.f;
        for (int k = beg; k < end; k++) {
            int e = g_eidx[k];
            float a = g_alpha[e * HMAX + g];
            acc += a * g_bufB[(size_t)g_srcv[e] * hstr + g * CC + c];
        }
        acc = gelu_exact(acc + bias[g * CC + c]);
        if (outF) {
            outF[(size_t)d * HC + g * CC + c] = acc;
        } else {
            outH[(size_t)d * KA + g * CC + c] = __float2half(acc);
        }
    }
}

// ---------------- host launch ----------------
extern "C" void kernel_launch(void* const* d_in, const int* in_sizes, int n_in,
                              void* d_out, int out_size) {
    const float* X  = (const float*)d_in[0];
    const int*   EI = (const int*)d_in[1];
    const float *W[5], *AS[5], *AD[5], *B[5];
    int idx = 2;
    for (int i = 0; i < 5; i++) {
        W[i]  = (const float*)d_in[idx++];
        AS[i] = (const float*)d_in[idx++];
        AD[i] = (const float*)d_in[idx++];
        B[i]  = (const float*)d_in[idx++];
    }
    float* out = (float*)d_out;

    __half *Ah, *Wh;
    float *bufB;
    cudaGetSymbolAddress((void**)&Ah, g_Ah);
    cudaGetSymbolAddress((void**)&Wh, g_Wh);
    cudaGetSymbolAddress((void**)&bufB, g_bufB);

    const int SMEM_DYN = 3 * STAGE_ELEMS * 2;   // 96 KB
    cudaFuncSetAttribute(k_gemm_mma, cudaFuncAttributeMaxDynamicSharedMemorySize, SMEM_DYN);

    const int KIN[5]  = {200, 800, 800, 800, 800};
    const int KP [5]  = {256, 832, 832, 832, 832};
    const int NC [5]  = {800, 800, 800, 800, 200};
    const int NP [5]  = {896, 896, 896, 896, 256};
    const int HD [5]  = {4, 4, 4, 4, 1};

    // launch order: slot 3 = first GEMM (ncu window)
    k_zero_A<<<(NPAD * KA / 8 + 255) / 256, 256>>>();                          // 0
    k_convert_X<<<(NPAD * 256 + 255) / 256, 256>>>(X);                         // 1
    k_convert_W<<<(KP[0] * NP[0] + 255) / 256, 256>>>(W[0], KIN[0], NC[0], KP[0], NP[0]); // 2

    for (int i = 0; i < 5; i++) {
        int Kp = KP[i], Np = NP[i], H = HD[i];
        if (i > 0)
            k_convert_W<<<(Kp * Np + 255) / 256, 256>>>(W[i], KIN[i], NC[i], Kp, Np);
        dim3 grid(Np / 128, NPAD / 128);
        k_gemm_mma<<<grid, 256, SMEM_DYN>>>(Ah, Wh, bufB, KA, Np, Kp / BK);    // i==0 -> slot 3
        if (i == 0) {
            k_zero_deg<<<(NN + 255) / 256, 256>>>();
            k_build_edges<<<(E2 + 255) / 256, 256>>>(EI);
            k_scan<<<1, 1024>>>();
            k_scatter<<<(E2 + 255) / 256, 256>>>();
        }
        k_alpha<<<NN, 32 * H>>>(AS[i], AD[i], H, Np);
        k_softmax<<<NN, 32 * H>>>(H, (i == 4) ? (out + (size_t)NN * 200) : nullptr);
        if (i < 4) {
            k_agg<<<NN, 64 * H>>>(B[i], H, Np, Ah, nullptr);
        } else {
            k_agg<<<NN, 64 * H>>>(B[i], H, Np, nullptr, out);
        }
    }
}

// round 8
// speedup vs baseline: 2.0796x; 1.5778x over previous
#include <cuda_runtime.h>
#include <cuda_fp16.h>
#include <math.h>

#define NN 10000
#define NPAD 10112          // 79 * 128
#define EE 100000
#define E2 110000
#define HMAX 4
#define CC 200
#define KA 832              // A col stride (13*64); layer0 uses cols 0..255

// ---------------- scratch (device globals; no allocs allowed) ----------------
__device__ __half g_Ah[NPAD * KA];        // fp16 activations
__device__ __half g_Wh[832 * 896];        // fp16 weights, [Kp][Np]
__device__ __half g_h[NPAD * 896];        // GEMM output h (fp16, padded stride)
__device__ float g_asrc[NN * HMAX];
__device__ float g_adst[NN * HMAX];
__device__ float g_den[NN * HMAX];        // 1/softmax_denominator
__device__ float g_alphaCSR[E2 * HMAX];   // CSR-ordered logits -> exp
__device__ int   g_srcv[E2];
__device__ int   g_dstv[E2];
__device__ int   g_srcCSR[E2];
__device__ int   g_eidx[E2];
__device__ int   g_deg[NN];
__device__ int   g_off[NN + 1];
__device__ int   g_pos[NN];

// ---------------- CSR construction ----------------
__global__ void k_zero_deg() {
    int i = blockIdx.x * blockDim.x + threadIdx.x;
    if (i < NN) g_deg[i] = 0;
}

__global__ void k_build_edges(const int* __restrict__ ei) {
    int e = blockIdx.x * blockDim.x + threadIdx.x;
    if (e >= E2) return;
    int s, d;
    if (e < EE) { s = ei[e]; d = ei[EE + e]; }
    else        { s = d = e - EE; }
    g_srcv[e] = s;
    g_dstv[e] = d;
    atomicAdd(&g_deg[d], 1);
}

__global__ void k_scan() {
    __shared__ int ssum[1024];
    const int CH = (NN + 1023) / 1024;
    int t = threadIdx.x;
    int start = t * CH;
    int local = 0;
    for (int i = 0; i < CH; i++) {
        int idx = start + i;
        if (idx < NN) local += g_deg[idx];
    }
    ssum[t] = local;
    __syncthreads();
    for (int d = 1; d < 1024; d <<= 1) {
        int v = (t >= d) ? ssum[t - d] : 0;
        __syncthreads();
        ssum[t] += v;
        __syncthreads();
    }
    int run = (t == 0) ? 0 : ssum[t - 1];
    for (int i = 0; i < CH; i++) {
        int idx = start + i;
        if (idx < NN) {
            g_off[idx] = run;
            g_pos[idx] = run;
            run += g_deg[idx];
        }
    }
    if (t == 1023) g_off[NN] = ssum[1023];
}

__global__ void k_scatter() {
    int e = blockIdx.x * blockDim.x + threadIdx.x;
    if (e >= E2) return;
    int p = atomicAdd(&g_pos[g_dstv[e]], 1);
    g_eidx[p] = e;
    g_srcCSR[p] = g_srcv[e];
}

// ---------------- conversions ----------------
__global__ void k_zero_A() {
    int i = blockIdx.x * blockDim.x + threadIdx.x;
    if (i < NPAD * KA / 8) ((uint4*)g_Ah)[i] = make_uint4(0, 0, 0, 0);
}

__global__ void k_convert_X(const float* __restrict__ X) {
    int idx = blockIdx.x * blockDim.x + threadIdx.x;
    if (idx >= NPAD * 256) return;
    int r = idx / 256, c = idx % 256;
    float v = (r < NN && c < 200) ? X[r * 200 + c] : 0.f;
    g_Ah[(size_t)r * KA + c] = __float2half(v);
}

__global__ void k_convert_W(const float* __restrict__ W, int K, int Nc, int Kp, int Np) {
    int idx = blockIdx.x * blockDim.x + threadIdx.x;
    if (idx >= Kp * Np) return;
    int r = idx / Np, c = idx % Np;
    float v = (r < K && c < Nc) ? W[r * Nc + c] : 0.f;
    g_Wh[idx] = __float2half(v);
}

// ---------------- fp16 mma.sync GEMM, BK=64, 3-stage cp.async ---------------
#define BK 64
#define STAGE_ELEMS 16384   // halfs per stage (32 KB): A 8192 + B 8192
#define SA_OFF 0
#define SB_OFF 8192

__device__ __forceinline__ unsigned sm_u32(const void* p) {
    return (unsigned)__cvta_generic_to_shared(p);
}

#define CP16(dst, src) \
    asm volatile("cp.async.cg.shared.global [%0], [%1], 16;" :: "r"(dst), "l"(src))
#define LDMX4(r, addr) \
    asm volatile("ldmatrix.sync.aligned.m8n8.x4.shared.b16 {%0,%1,%2,%3}, [%4];" \
        : "=r"((r)[0]), "=r"((r)[1]), "=r"((r)[2]), "=r"((r)[3]) : "r"(addr))
#define LDMX4T(r, addr) \
    asm volatile("ldmatrix.sync.aligned.m8n8.x4.trans.shared.b16 {%0,%1,%2,%3}, [%4];" \
        : "=r"((r)[0]), "=r"((r)[1]), "=r"((r)[2]), "=r"((r)[3]) : "r"(addr))
#define MMAF16(d, a, b) \
    asm volatile("mma.sync.aligned.m16n8k16.row.col.f32.f16.f16.f32 " \
        "{%0,%1,%2,%3}, {%4,%5,%6,%7}, {%8,%9}, {%0,%1,%2,%3};" \
        : "+f"((d)[0]), "+f"((d)[1]), "+f"((d)[2]), "+f"((d)[3]) \
        : "r"((a)[0]), "r"((a)[1]), "r"((a)[2]), "r"((a)[3]), "r"((b)[0]), "r"((b)[1]))

__global__ __launch_bounds__(256, 2) void k_gemm_mma(
    const __half* __restrict__ A, const __half* __restrict__ B,
    __half* __restrict__ C, int lda, int Cstr, int nk)
{
    extern __shared__ __half smem[];
    int t = threadIdx.x;
    int lane = t & 31;
    int w = t >> 5;
    int wm = (w >> 2) * 64;
    int wn = (w & 3) * 32;
    int bm = blockIdx.y * 128;
    int bn = blockIdx.x * 128;

    float acc[4][4][4];
    #pragma unroll
    for (int i = 0; i < 4; i++)
        #pragma unroll
        for (int j = 0; j < 4; j++)
            #pragma unroll
            for (int x = 0; x < 4; x++) acc[i][j][x] = 0.f;

    auto load_stage = [&](int kt, int s) {
        __half* st = smem + s * STAGE_ELEMS;
        #pragma unroll
        for (int i = 0; i < 4; i++) {
            int q = t + i * 256;
            int r = q >> 3, ch = q & 7;
            const __half* src = A + (size_t)(bm + r) * lda + kt * BK + ch * 8;
            CP16(sm_u32(st + SA_OFF + r * 64 + ((ch ^ (r & 7)) << 3)), src);
        }
        #pragma unroll
        for (int i = 0; i < 4; i++) {
            int q = t + i * 256;
            int kr = q >> 4, c = q & 15;
            size_t goff = (size_t)(kt * BK + kr) * Cstr + bn + c * 8;
            CP16(sm_u32(st + SB_OFF + kr * 128 + ((c ^ (kr & 7)) << 3)), B + goff);
        }
    };

    #pragma unroll
    for (int s = 0; s < 2; s++) {
        if (s < nk) load_stage(s, s);
        asm volatile("cp.async.commit_group;");
    }

    for (int kt = 0; kt < nk; kt++) {
        if (kt + 1 < nk) asm volatile("cp.async.wait_group 1;");
        else             asm volatile("cp.async.wait_group 0;");
        __syncthreads();
        if (kt + 2 < nk) {
            load_stage(kt + 2, (kt + 2) % 3);
            asm volatile("cp.async.commit_group;");
        }

        __half* st = smem + (kt % 3) * STAGE_ELEMS;
        #pragma unroll
        for (int ks = 0; ks < 4; ks++) {
            unsigned ah[4][4];
            int kc = ks * 2 + (lane >> 4);
            #pragma unroll
            for (int mi = 0; mi < 4; mi++) {
                int r = wm + mi * 16 + (lane & 15);
                LDMX4(ah[mi], sm_u32(st + SA_OFF + r * 64 + ((kc ^ (r & 7)) << 3)));
            }
            unsigned bf[2][4];
            int kb = ks * 16 + (lane & 15);
            #pragma unroll
            for (int nq = 0; nq < 2; nq++) {
                int n = wn + nq * 16 + (lane >> 4) * 8;
                int c = n >> 3;
                LDMX4T(bf[nq], sm_u32(st + SB_OFF + kb * 128 + ((c ^ (kb & 7)) << 3)));
            }
            #pragma unroll
            for (int mi = 0; mi < 4; mi++)
                #pragma unroll
                for (int j = 0; j < 4; j++)
                    MMAF16(acc[mi][j], ah[mi], (&bf[j >> 1][(j & 1) * 2]));
        }
        __syncthreads();
    }

    // epilogue: fp16 output (all dims padded; unconditional)
    #pragma unroll
    for (int mi = 0; mi < 4; mi++)
        #pragma unroll
        for (int j = 0; j < 4; j++) {
            int row = bm + wm + mi * 16 + (lane >> 2);
            int col = bn + wn + j * 8 + (lane & 3) * 2;
            *(__half2*)(C + (size_t)row * Cstr + col) =
                __floats2half2_rn(acc[mi][j][0], acc[mi][j][1]);
            *(__half2*)(C + (size_t)(row + 8) * Cstr + col) =
                __floats2half2_rn(acc[mi][j][2], acc[mi][j][3]);
        }
}

// ---------------- attention coefficients (fp16 h) ----------------
__global__ void k_alpha(const float* __restrict__ asW,
                        const float* __restrict__ adW, int H, int hstr) {
    int n = blockIdx.x;
    int h = threadIdx.x >> 5;
    int lane = threadIdx.x & 31;
    if (h >= H) return;
    const __half2* hrow = (const __half2*)(g_h + (size_t)n * hstr + h * CC);
    const float* pa = asW + h * CC;
    const float* pd = adW + h * CC;
    float s1 = 0.f, s2 = 0.f;
    for (int c2 = lane; c2 < CC / 2; c2 += 32) {
        float2 v = __half22float2(hrow[c2]);
        s1 += v.x * pa[2 * c2] + v.y * pa[2 * c2 + 1];
        s2 += v.x * pd[2 * c2] + v.y * pd[2 * c2 + 1];
    }
    #pragma unroll
    for (int o = 16; o; o >>= 1) {
        s1 += __shfl_xor_sync(0xffffffffu, s1, o);
        s2 += __shfl_xor_sync(0xffffffffu, s2, o);
    }
    if (lane == 0) {
        g_asrc[n * HMAX + h] = s1;
        g_adst[n * HMAX + h] = s2;
    }
}

// ---------------- segment softmax: 2 passes, CSR-ordered ----------------
__global__ void k_softmax(int H) {
    int d = blockIdx.x;
    int h = threadIdx.x >> 5;
    int lane = threadIdx.x & 31;
    if (h >= H) return;
    int beg = g_off[d], end = g_off[d + 1];
    float ad = g_adst[d * HMAX + h];

    // pass 1: gather logits into CSR-ordered buffer, track max
    float mx = -INFINITY;
    for (int k = beg + lane; k < end; k += 32) {
        float v = g_asrc[g_srcCSR[k] * HMAX + h] + ad;
        v = v > 0.f ? v : 0.2f * v;
        g_alphaCSR[k * HMAX + h] = v;
        mx = fmaxf(mx, v);
    }
    #pragma unroll
    for (int o = 16; o; o >>= 1) mx = fmaxf(mx, __shfl_xor_sync(0xffffffffu, mx, o));

    // pass 2: exp + sum (contiguous reads)
    float sum = 0.f;
    for (int k = beg + lane; k < end; k += 32) {
        float ex = expf(g_alphaCSR[k * HMAX + h] - mx);
        g_alphaCSR[k * HMAX + h] = ex;
        sum += ex;
    }
    #pragma unroll
    for (int o = 16; o; o >>= 1) sum += __shfl_xor_sync(0xffffffffu, sum, o);
    if (lane == 0) g_den[d * HMAX + h] = 1.f / sum;
}

// ---------------- aggregation + bias + gelu ----------------
__device__ __forceinline__ float gelu_exact(float v) {
    return 0.5f * v * (1.0f + erff(v * 0.70710678118654752f));
}

__global__ void k_agg(const float* __restrict__ bias, int H, int hstr,
                      __half* __restrict__ outH, float* __restrict__ outF,
                      float* __restrict__ attn_out) {
    int d = blockIdx.x;
    int g = threadIdx.x >> 6;
    int c0 = threadIdx.x & 63;
    if (g >= H) return;
    int beg = g_off[d], end = g_off[d + 1];
    float inv = g_den[d * HMAX + g];
    int HC = H * CC;

    if (attn_out && g == 0) {
        for (int k = beg + c0; k < end; k += 64)
            attn_out[g_eidx[k]] = g_alphaCSR[k * HMAX] * inv;
    }

    for (int c2 = c0; c2 < CC / 2; c2 += 64) {
        float2 acc = make_float2(0.f, 0.f);
        for (int k = beg; k < end; k++) {
            float a = g_alphaCSR[k * HMAX + g];
            float2 f = __half22float2(
                *(const __half2*)(g_h + (size_t)g_srcCSR[k] * hstr + g * CC + 2 * c2));
            acc.x += a * f.x;
            acc.y += a * f.y;
        }
        int c = 2 * c2;
        float o0 = gelu_exact(acc.x * inv + bias[g * CC + c]);
        float o1 = gelu_exact(acc.y * inv + bias[g * CC + c + 1]);
        if (outF) {
            outF[(size_t)d * HC + g * CC + c]     = o0;
            outF[(size_t)d * HC + g * CC + c + 1] = o1;
        } else {
            *(__half2*)(outH + (size_t)d * KA + g * CC + c) = __floats2half2_rn(o0, o1);
        }
    }
}

// ---------------- host launch ----------------
extern "C" void kernel_launch(void* const* d_in, const int* in_sizes, int n_in,
                              void* d_out, int out_size) {
    const float* X  = (const float*)d_in[0];
    const int*   EI = (const int*)d_in[1];
    const float *W[5], *AS[5], *AD[5], *B[5];
    int idx = 2;
    for (int i = 0; i < 5; i++) {
        W[i]  = (const float*)d_in[idx++];
        AS[i] = (const float*)d_in[idx++];
        AD[i] = (const float*)d_in[idx++];
        B[i]  = (const float*)d_in[idx++];
    }
    float* out = (float*)d_out;

    __half *Ah, *Wh, *hbuf;
    cudaGetSymbolAddress((void**)&Ah, g_Ah);
    cudaGetSymbolAddress((void**)&Wh, g_Wh);
    cudaGetSymbolAddress((void**)&hbuf, g_h);

    const int SMEM_DYN = 3 * STAGE_ELEMS * 2;   // 96 KB
    cudaFuncSetAttribute(k_gemm_mma, cudaFuncAttributeMaxDynamicSharedMemorySize, SMEM_DYN);

    const int KIN[5]  = {200, 800, 800, 800, 800};
    const int KP [5]  = {256, 832, 832, 832, 832};
    const int NC [5]  = {800, 800, 800, 800, 200};
    const int NP [5]  = {896, 896, 896, 896, 256};
    const int HD [5]  = {4, 4, 4, 4, 1};

    // launch order: slot 3 = first GEMM (ncu window)
    k_zero_A<<<(NPAD * KA / 8 + 255) / 256, 256>>>();                          // 0
    k_convert_X<<<(NPAD * 256 + 255) / 256, 256>>>(X);                         // 1
    k_convert_W<<<(KP[0] * NP[0] + 255) / 256, 256>>>(W[0], KIN[0], NC[0], KP[0], NP[0]); // 2

    for (int i = 0; i < 5; i++) {
        int Kp = KP[i], Np = NP[i], H = HD[i];
        if (i > 0)
            k_convert_W<<<(Kp * Np + 255) / 256, 256>>>(W[i], KIN[i], NC[i], Kp, Np);
        dim3 grid(Np / 128, NPAD / 128);
        k_gemm_mma<<<grid, 256, SMEM_DYN>>>(Ah, Wh, hbuf, KA, Np, Kp / BK);    // i==0 -> slot 3
        if (i == 0) {
            k_zero_deg<<<(NN + 255) / 256, 256>>>();
            k_build_edges<<<(E2 + 255) / 256, 256>>>(EI);
            k_scan<<<1, 1024>>>();
            k_scatter<<<(E2 + 255) / 256, 256>>>();
        }
        k_alpha<<<NN, 32 * H>>>(AS[i], AD[i], H, Np);
        k_softmax<<<NN, 32 * H>>>(H);
        if (i < 4) {
            k_agg<<<NN, 64 * H>>>(B[i], H, Np, Ah, nullptr, nullptr);
        } else {
            k_agg<<<NN, 64 * H>>>(B[i], H, Np, nullptr, out, out + (size_t)NN * 200);
        }
    }
}